// round 16
// baseline (speedup 1.0000x reference)
#include <cuda_runtime.h>
#include <cuda_fp16.h>
#include <math.h>

#define NBASE 40000
#define NJOINT 480000
#define NFOOT 160000
#define HDIM 128
#define NEG_SLOPE 0.2f
#define RSTR 481280      // padded per-role segment stride (= 470*1024)
#define NBLK 470         // 1024-elem scan blocks per segment

// ---------------- scratch (device globals; ~1.0 GB, linker-safe) ----------------
__device__ __half g_bufA[(size_t)680000 * 128];   // x / agg ping-pong (fp16, post-relu)
__device__ __half g_bufB[(size_t)680000 * 128];
__device__ __half g_pool[(size_t)1680000 * 128];  // compact xl/xr rows (fp16)
__device__ __half g_Whi[40 * 16384];              // fp16 hi/lo split of W^T ([n][k])
__device__ __half g_Wlo[40 * 16384];
__device__ int g_rank[10 * RSTR];
__device__ int g_list[10 * RSTR];
__device__ int g_scan[10 * RSTR];
__device__ int g_deg[5 * RSTR];
__device__ int g_off5[5 * RSTR];
__device__ int g_cur5[5 * RSTR];
__device__ int g_csr[960000];
__device__ int g_cnt[16];
__device__ int g_part[10 * 512];

// ---------------- weight prep: transpose + fp16 hi/lo split ----------------
__global__ void wprep_k(const float* __restrict__ Wl, const float* __restrict__ Wr,
                        __half* __restrict__ hi, __half* __restrict__ lo) {
    int idx = blockIdx.x * 256 + threadIdx.x;
    if (idx >= 40 * 16384) return;
    int m = idx >> 14, e = idx & 16383;
    int n = e >> 7, k = e & 127;
    const float* src = (m < 20) ? (Wl + (size_t)m * 16384) : (Wr + (size_t)(m - 20) * 16384);
    float v = src[k * 128 + n];
    __half h = __float2half(v);
    __half l = __float2half(v - __half2float(h));
    hi[idx] = h; lo[idx] = l;
}

// vectorized encoder (writes post-relu fp16)
__global__ void encode_k(const float* __restrict__ x, const float* __restrict__ W,
                         const float* __restrict__ b, __half* __restrict__ y, int N, int K) {
    int idx = blockIdx.x * 256 + threadIdx.x;
    if (idx >= N * 32) return;
    int n = idx >> 5, q = idx & 31;
    float4 acc = ((const float4*)b)[q];
    for (int k = 0; k < K; k++) {
        float xv = __ldg(x + (size_t)n * K + k);
        float4 w = ((const float4*)W)[k * 32 + q];
        acc.x += xv * w.x; acc.y += xv * w.y; acc.z += xv * w.z; acc.w += xv * w.w;
    }
    __half2 h0 = __floats2half2_rn(fmaxf(acc.x, 0.f), fmaxf(acc.y, 0.f));
    __half2 h1 = __floats2half2_rn(fmaxf(acc.z, 0.f), fmaxf(acc.w, 0.f));
    uint2 p;
    p.x = *(unsigned*)&h0;
    p.y = *(unsigned*)&h1;
    *(uint2*)(y + (size_t)n * 128 + q * 4) = p;
}

// ---------------- batched prep ----------------
struct EL {
    const int* src[5];
    const int* dst[5];
    int cumE[6];
};
struct NArr { int N[10]; };

__global__ void mark_all_k(EL el, int total) {
    int gi = blockIdx.x * 256 + threadIdx.x;
    if (gi >= 2 * total) return;
    int side = gi >= total;
    int j = gi - side * total;
    int t = 0;
    while (j >= el.cumE[t + 1]) t++;
    int e = j - el.cumE[t];
    int node = side ? el.dst[t][e] : el.src[t][e];
    g_rank[(2 * t + side) * RSTR + node] = 1;
}

__global__ void bscan1_k(const int* __restrict__ v, int* __restrict__ out,
                         int* __restrict__ part) {
    __shared__ int sh[1024];
    int r = blockIdx.x / NBLK, j = blockIdx.x % NBLK;
    int i = r * RSTR + j * 1024 + threadIdx.x;
    int val = v[i];
    sh[threadIdx.x] = val;
    __syncthreads();
#pragma unroll
    for (int o = 1; o < 1024; o <<= 1) {
        int t = (threadIdx.x >= o) ? sh[threadIdx.x - o] : 0;
        __syncthreads();
        sh[threadIdx.x] += t;
        __syncthreads();
    }
    int incl = sh[threadIdx.x];
    out[i] = incl - val;
    if (threadIdx.x == 1023) part[r * 512 + j] = incl;
}
__global__ void bscan2_k(int* part) {
    __shared__ int sh[512];
    int r = blockIdx.x;
    int v = (threadIdx.x < NBLK) ? part[r * 512 + threadIdx.x] : 0;
    sh[threadIdx.x] = v;
    __syncthreads();
#pragma unroll
    for (int o = 1; o < 512; o <<= 1) {
        int t = (threadIdx.x >= o) ? sh[threadIdx.x - o] : 0;
        __syncthreads();
        sh[threadIdx.x] += t;
        __syncthreads();
    }
    if (threadIdx.x < NBLK) part[r * 512 + threadIdx.x] = sh[threadIdx.x] - v;
}
__global__ void bscan3_k(int* __restrict__ out, const int* __restrict__ part,
                         int* __restrict__ cur) {
    int r = blockIdx.x / NBLK, j = blockIdx.x % NBLK;
    int i = r * RSTR + j * 1024 + threadIdx.x;
    int v = out[i] + part[r * 512 + j];
    out[i] = v;
    if (cur) cur[i] = v;
}

__global__ void bcompact_k(NArr na) {
    int i = blockIdx.x * 256 + threadIdx.x;
    if (i >= 10 * RSTR) return;
    int r = i / RSTR, li = i % RSTR;
    if (li == na.N[r]) g_cnt[r] = g_scan[i];
    if (li >= na.N[r]) return;
    if (g_rank[i]) {
        int pos = g_scan[i];
        g_list[r * RSTR + pos] = li;
        g_rank[i] = pos;
    } else {
        g_rank[i] = -1;
    }
}

__global__ void bhist_k(EL el, int total) {
    int j = blockIdx.x * 256 + threadIdx.x;
    if (j >= total) return;
    int t = 0;
    while (j >= el.cumE[t + 1]) t++;
    int e = j - el.cumE[t];
    atomicAdd(&g_deg[t * RSTR + el.dst[t][e]], 1);
}
__global__ void bfill_k(EL el, int total) {
    int j = blockIdx.x * 256 + threadIdx.x;
    if (j >= total) return;
    int t = 0;
    while (j >= el.cumE[t + 1]) t++;
    int e = j - el.cumE[t];
    int d = el.dst[t][e];
    int p = atomicAdd(&g_cur5[t * RSTR + d], 1);
    g_csr[el.cumE[t] + p] = g_rank[(2 * t) * RSTR + el.src[t][e]];
}

// ---------------- batched gather-GEMM (fp16 A exact, fp16 hi/lo W, 2-term MMA) ----------------
#define SAE 8704    // 64*136 fp16 elems (A)
#define SBE 17408   // 128*136 fp16 elems (B)

#define LDSM4(R, addr) asm volatile( \
    "ldmatrix.sync.aligned.m8n8.x4.shared.b16 {%0,%1,%2,%3}, [%4];" \
    : "=r"((R)[0]), "=r"((R)[1]), "=r"((R)[2]), "=r"((R)[3]) : "r"(addr))

#define MMAF16(C, A, b0, b1) asm volatile( \
    "mma.sync.aligned.m16n8k16.row.col.f32.f16.f16.f32 " \
    "{%0,%1,%2,%3},{%4,%5,%6,%7},{%8,%9},{%0,%1,%2,%3};" \
    : "+f"((C)[0]), "+f"((C)[1]), "+f"((C)[2]), "+f"((C)[3]) \
    : "r"((A)[0]), "r"((A)[1]), "r"((A)[2]), "r"((A)[3]), "r"(b0), "r"(b1))

static __device__ __forceinline__ void cpasync16(unsigned dst, const void* src, int sz) {
    asm volatile("cp.async.cg.shared.global [%0], [%1], 16, %2;" :: "r"(dst), "l"(src), "r"(sz));
}

struct GR {
    const __half* A;
    const int* rowlist;
    const int* cntPtr;
    const __half* Bhi;
    const __half* Blo;
    const float* bias;
    __half* out;
};
struct GB { GR r[10]; int cum[11]; int n; };

__global__ void __launch_bounds__(256, 2) gemm_batch_k(GB gb) {
    int b = blockIdx.x;
    int k = 0;
    while (k < gb.n - 1 && b >= gb.cum[k + 1]) k++;
    GR R = gb.r[k];
    const int cnt = *R.cntPtr;
    const int row0 = (b - gb.cum[k]) * 64;
    if (row0 >= cnt) return;

    extern __shared__ __half smem[];
    const int tid = threadIdx.x;
    unsigned sA = (unsigned)__cvta_generic_to_shared(smem);
    unsigned sB = sA + SAE * 2;

#pragma unroll
    for (int i = 0; i < 8; i++) {
        int chunk = tid + i * 256;
        int row = chunk >> 4;
        int col = (chunk & 15) * 8;
        size_t off = (size_t)row * 128 + col;
        unsigned d = sB + (unsigned)(row * 136 + col) * 2;
        cpasync16(d, R.Bhi + off, 16);
        cpasync16(d + SBE * 2, R.Blo + off, 16);
    }
#pragma unroll
    for (int i = 0; i < 4; i++) {
        int chunk = tid + i * 256;
        int row = chunk >> 4;
        int col = (chunk & 15) * 8;
        int ok = (row0 + row) < cnt;
        int node = ok ? R.rowlist[row0 + row] : 0;
        unsigned d = sA + (unsigned)(row * 136 + col) * 2;
        cpasync16(d, R.A + (size_t)node * 128 + col, ok ? 16 : 0);
    }
    asm volatile("cp.async.commit_group;");
    asm volatile("cp.async.wait_group 0;");
    __syncthreads();

    int warp = tid >> 5, lane = tid & 31;
    int m0 = (warp >> 2) * 32;
    int n0 = (warp & 3) * 32;
    int frow = lane & 15;
    int fcolo = (lane >> 4) * 8;

    float acc[2][4][4];
#pragma unroll
    for (int a = 0; a < 2; a++)
#pragma unroll
        for (int c = 0; c < 4; c++)
#pragma unroll
            for (int r = 0; r < 4; r++) acc[a][c][r] = 0.f;

    for (int ks = 0; ks < 8; ks++) {
        int acol = ks * 16 + fcolo;
        unsigned ah[2][4];
#pragma unroll
        for (int mt = 0; mt < 2; mt++) {
            unsigned ad = sA + (unsigned)((m0 + mt * 16 + frow) * 136 + acol) * 2;
            LDSM4(ah[mt], ad);
        }
        unsigned bh[2][4], blx[2][4];
#pragma unroll
        for (int p = 0; p < 2; p++) {
            unsigned bd = sB + (unsigned)((n0 + p * 16 + frow) * 136 + acol) * 2;
            LDSM4(bh[p], bd);
            LDSM4(blx[p], bd + SBE * 2);
        }
#pragma unroll
        for (int mt = 0; mt < 2; mt++)
#pragma unroll
            for (int nt = 0; nt < 4; nt++) {
                int p = nt >> 1, o = nt & 1;
                MMAF16(acc[mt][nt], ah[mt], bh[p][o], bh[p][2 + o]);
                MMAF16(acc[mt][nt], ah[mt], blx[p][o], blx[p][2 + o]);
            }
    }

    int crow = lane >> 2, ccol = (lane & 3) * 2;
#pragma unroll
    for (int nt = 0; nt < 4; nt++) {
        int col = n0 + nt * 8 + ccol;
        float b0v = R.bias[col], b1v = R.bias[col + 1];
#pragma unroll
        for (int mt = 0; mt < 2; mt++) {
            int r = row0 + m0 + mt * 16 + crow;
            if (r < cnt)
                *(__half2*)(R.out + (size_t)r * 128 + col) =
                    __floats2half2_rn(acc[mt][nt][0] + b0v, acc[mt][nt][1] + b1v);
            if (r + 8 < cnt)
                *(__half2*)(R.out + (size_t)(r + 8) * 128 + col) =
                    __floats2half2_rn(acc[mt][nt][2] + b0v, acc[mt][nt][3] + b1v);
        }
    }
}

// ---------------- edge kernel: 16 lanes/dst (2 dsts per warp), deg-1 fast path ----------------
struct EdgeT {
    const __half* xl;
    const __half* xr;
    const int* csr;
    const int* off;
    const int* rank;
    const float* att;
    const float* bias;
};

struct F8 { float v[8]; };

static __device__ __forceinline__ F8 ldh8(const __half* p) {
    uint4 raw = *(const uint4*)p;
    const __half2* hp = (const __half2*)&raw;
    F8 f;
#pragma unroll
    for (int i = 0; i < 4; i++) {
        float2 t = __half22float2(hp[i]);
        f.v[2 * i] = t.x; f.v[2 * i + 1] = t.y;
    }
    return f;
}
static __device__ __forceinline__ F8 ldf8(const float* p) {
    float4 a = ((const float4*)p)[0];
    float4 b = ((const float4*)p)[1];
    F8 f;
    f.v[0] = a.x; f.v[1] = a.y; f.v[2] = a.z; f.v[3] = a.w;
    f.v[4] = b.x; f.v[5] = b.y; f.v[6] = b.z; f.v[7] = b.w;
    return f;
}
static __device__ __forceinline__ void addF8(F8& r, const F8& x) {
#pragma unroll
    for (int i = 0; i < 8; i++) r.v[i] += x.v[i];
}

static __device__ __forceinline__ float logit8(const F8& x, const F8& xr, const F8& at) {
    float s = 0.f;
#pragma unroll
    for (int i = 0; i < 8; i++) {
        float t = x.v[i] + xr.v[i];
        t = t > 0.f ? t : NEG_SLOPE * t;
        s += t * at.v[i];
    }
    return s;
}

#define RED16(p) _Pragma("unroll") for (int o_ = 8; o_; o_ >>= 1) p += __shfl_xor_sync(0xffffffffu, p, o_)

// deg>=2 online softmax; first edge preloaded in x1
static __device__ __forceinline__ void soft_multi(const EdgeT& t, int d, int s0, int s1,
                                                  int lane16, F8 x1, F8& r) {
    int cr = t.rank[d];
    F8 xr = ldh8(t.xr + (size_t)cr * 128 + lane16 * 8);
    F8 at = ldf8(t.att + lane16 * 8);
    float p0 = logit8(x1, xr, at);
    RED16(p0);
    float m = p0, den = 1.f;
    F8 a = x1;
    int e = s0 + 1;
    for (; e + 1 < s1; e += 2) {
        int si0 = t.csr[e], si1 = t.csr[e + 1];
        F8 y0 = ldh8(t.xl + (size_t)si0 * 128 + lane16 * 8);
        F8 y1 = ldh8(t.xl + (size_t)si1 * 128 + lane16 * 8);
        float q0 = logit8(y0, xr, at);
        float q1 = logit8(y1, xr, at);
        RED16(q0);
        RED16(q1);
        float mn = fmaxf(m, fmaxf(q0, q1));
        float c = __expf(m - mn);
        float w0 = __expf(q0 - mn);
        float w1 = __expf(q1 - mn);
        den = den * c + w0 + w1;
#pragma unroll
        for (int i = 0; i < 8; i++)
            a.v[i] = a.v[i] * c + w0 * y0.v[i] + w1 * y1.v[i];
        m = mn;
    }
    if (e < s1) {
        int si = t.csr[e];
        F8 yv = ldh8(t.xl + (size_t)si * 128 + lane16 * 8);
        float q = logit8(yv, xr, at);
        RED16(q);
        float mn = fmaxf(m, q);
        float c = __expf(m - mn);
        float w = __expf(q - mn);
        den = den * c + w;
#pragma unroll
        for (int i = 0; i < 8; i++) a.v[i] = a.v[i] * c + w * yv.v[i];
    }
    float inv = 1.f / den;
#pragma unroll
    for (int i = 0; i < 8; i++) r.v[i] += a.v[i] * inv;
}

static __device__ __forceinline__ void proc_fast(const EdgeT& t, int d, int lane16, F8& r) {
    F8 bb = ldf8(t.bias + lane16 * 8);
    addF8(r, bb);
    int s0 = t.off[d], s1 = t.off[d + 1];
    if (s1 <= s0) return;
    int fi = t.csr[s0];
    F8 x1 = ldh8(t.xl + (size_t)fi * 128 + lane16 * 8);
    if (s1 - s0 == 1) { addF8(r, x1); return; }   // softmax of 1 elem == 1
    soft_multi(t, d, s0, s1, lane16, x1, r);
}

// joint dst: three edge types with cross-type prefetch
static __device__ __forceinline__ void edge_joint3(const EdgeT& tA, const EdgeT& tB,
                                                   const EdgeT& tC, int d, int lane16,
                                                   F8& r) {
    int s0a = tA.off[d], s1a = tA.off[d + 1];
    int s0b = tB.off[d], s1b = tB.off[d + 1];
    int s0c = tC.off[d], s1c = tC.off[d + 1];
    {
        F8 b0 = ldf8(tA.bias + lane16 * 8);
        F8 b1 = ldf8(tB.bias + lane16 * 8);
        F8 b2 = ldf8(tC.bias + lane16 * 8);
#pragma unroll
        for (int i = 0; i < 8; i++) r.v[i] += b0.v[i] + b1.v[i] + b2.v[i];
    }
    int dA = s1a - s0a, dB = s1b - s0b, dC = s1c - s0c;
    int fiA = 0, fiB = 0, fiC = 0;
    if (dA > 0) fiA = tA.csr[s0a];
    if (dB > 0) fiB = tB.csr[s0b];
    if (dC > 0) fiC = tC.csr[s0c];
    F8 xA, xB, xC;
#pragma unroll
    for (int i = 0; i < 8; i++) { xA.v[i] = 0.f; xB.v[i] = 0.f; xC.v[i] = 0.f; }
    if (dA > 0) xA = ldh8(tA.xl + (size_t)fiA * 128 + lane16 * 8);
    if (dB > 0) xB = ldh8(tB.xl + (size_t)fiB * 128 + lane16 * 8);
    if (dC > 0) xC = ldh8(tC.xl + (size_t)fiC * 128 + lane16 * 8);
    if (dA == 1) addF8(r, xA);
    else if (dA > 1) soft_multi(tA, d, s0a, s1a, lane16, xA, r);
    if (dB == 1) addF8(r, xB);
    else if (dB > 1) soft_multi(tB, d, s0b, s1b, lane16, xB, r);
    if (dC == 1) addF8(r, xC);
    else if (dC > 1) soft_multi(tC, d, s0c, s1c, lane16, xC, r);
}

// store with fused relu
static __device__ __forceinline__ void store_agg(__half* agg, int d, int lane16, const F8& r) {
    uint4 packed;
    __half2* hp = (__half2*)&packed;
#pragma unroll
    for (int i = 0; i < 4; i++)
        hp[i] = __floats2half2_rn(fmaxf(r.v[2 * i], 0.f), fmaxf(r.v[2 * i + 1], 0.f));
    *(uint4*)(agg + (size_t)d * 128 + lane16 * 8) = packed;
}

struct LayerED {
    EdgeT tJ0, tJ1, tJ2;
    EdgeT tB;
    EdgeT tF;
    __half *aggJ, *aggB, *aggF;
    int bB0, bF0;         // block ranges (16 dsts per block)
    const float* Wdec;
    const float* bdec;
    float* dec_out;
    int doDecode;
};

__global__ void edge_layer_k(LayerED L) {
    int blk = blockIdx.x;
    int w = threadIdx.x >> 5;
    int lane = threadIdx.x & 31;
    int sub = lane >> 4;
    int lane16 = lane & 15;
    F8 r;
#pragma unroll
    for (int i = 0; i < 8; i++) r.v[i] = 0.f;
    if (blk < L.bB0) {
        int d = blk * 16 + w * 2 + sub;
        edge_joint3(L.tJ0, L.tJ1, L.tJ2, d, lane16, r);
        store_agg(L.aggJ, d, lane16, r);
    } else if (blk < L.bF0) {
        int d = (blk - L.bB0) * 16 + w * 2 + sub;
        proc_fast(L.tB, d, lane16, r);
        store_agg(L.aggB, d, lane16, r);
    } else {
        int d = (blk - L.bF0) * 16 + w * 2 + sub;
        proc_fast(L.tF, d, lane16, r);
        if (!L.doDecode) {
            store_agg(L.aggF, d, lane16, r);
        } else {
            // fused decoder: relu + [128]x[128,3] matvec, 16-lane groups
#pragma unroll
            for (int i = 0; i < 8; i++) r.v[i] = fmaxf(r.v[i], 0.f);
            const float* W = L.Wdec;
            int h = lane16 * 8;
            float s0 = 0.f, s1 = 0.f, s2 = 0.f;
#pragma unroll
            for (int i = 0; i < 8; i++) {
                float v = r.v[i];
                s0 += v * W[(h + i) * 3 + 0];
                s1 += v * W[(h + i) * 3 + 1];
                s2 += v * W[(h + i) * 3 + 2];
            }
            RED16(s0); RED16(s1); RED16(s2);
            if (lane16 == 0) {
                L.dec_out[d * 3 + 0] = s0 + L.bdec[0];
                L.dec_out[d * 3 + 1] = s1 + L.bdec[1];
                L.dec_out[d * 3 + 2] = s2 + L.bdec[2];
            }
        }
    }
}

// ---------------- host orchestration ----------------
extern "C" void kernel_launch(void* const* d_in, const int* in_sizes, int n_in,
                              void* d_out, int out_size) {
    int I[27];
    if (in_sizes[1] == 768) {
        const int m[27] = {0, 3, 6, 1, 2, 4, 5, 7, 8,
                           19, 20, 21, 22, 23, 24, 25, 26,
                           9, 10, 11, 12, 13, 14, 15, 16, 17, 18};
        for (int i = 0; i < 27; i++) I[i] = m[i];
    } else {
        for (int i = 0; i < 27; i++) I[i] = i;
    }

    const float* x_in[3] = {(const float*)d_in[I[0]], (const float*)d_in[I[1]], (const float*)d_in[I[2]]};
    const float* Wenc[3] = {(const float*)d_in[I[3]], (const float*)d_in[I[5]], (const float*)d_in[I[7]]};
    const float* benc[3] = {(const float*)d_in[I[4]], (const float*)d_in[I[6]], (const float*)d_in[I[8]]};
    const float* Wl = (const float*)d_in[I[9]];
    const float* bl = (const float*)d_in[I[10]];
    const float* Wr = (const float*)d_in[I[11]];
    const float* br = (const float*)d_in[I[12]];
    const float* att = (const float*)d_in[I[13]];
    const float* cb = (const float*)d_in[I[14]];
    const float* Wdec = (const float*)d_in[I[15]];
    const float* bdec = (const float*)d_in[I[16]];
    const int *srcA[5], *dstA[5];
    int E[5];
    for (int t = 0; t < 5; t++) {
        srcA[t] = (const int*)d_in[I[17 + 2 * t]];
        dstA[t] = (const int*)d_in[I[18 + 2 * t]];
        E[t] = in_sizes[I[17 + 2 * t]];
    }

    __half *bufA, *bufB, *pool, *Whi, *Wlo;
    int *rankB, *listB, *scanB, *degB, *off5, *cur5, *csrB, *cnt, *part;
    cudaGetSymbolAddress((void**)&bufA, g_bufA);
    cudaGetSymbolAddress((void**)&bufB, g_bufB);
    cudaGetSymbolAddress((void**)&pool, g_pool);
    cudaGetSymbolAddress((void**)&Whi, g_Whi);
    cudaGetSymbolAddress((void**)&Wlo, g_Wlo);
    cudaGetSymbolAddress((void**)&rankB, g_rank);
    cudaGetSymbolAddress((void**)&listB, g_list);
    cudaGetSymbolAddress((void**)&scanB, g_scan);
    cudaGetSymbolAddress((void**)&degB, g_deg);
    cudaGetSymbolAddress((void**)&off5, g_off5);
    cudaGetSymbolAddress((void**)&cur5, g_cur5);
    cudaGetSymbolAddress((void**)&csrB, g_csr);
    cudaGetSymbolAddress((void**)&cnt, g_cnt);
    cudaGetSymbolAddress((void**)&part, g_part);

    const int Nn[3] = {NBASE, NJOINT, NFOOT};
    const int Kin[3] = {6, 2, 4};
    const size_t XOFF[3] = {0, (size_t)NBASE * 128, (size_t)(NBASE + NJOINT) * 128};
    const int sT[5] = {0, 1, 1, 1, 2};
    const int dT[5] = {1, 0, 1, 2, 1};
    const size_t POOL[10] = {0, 40000, 200000, 360000, 400000, 720000, 1040000, 1200000, 1360000, 1520000};
    const int GRIDR[10] = {625, 2500, 2500, 625, 5000, 5000, 2500, 2500, 2500, 2500};

    const int SMEM = (SAE + 2 * SBE) * 2;   // 87040 B -> 2 CTAs/SM
    cudaFuncSetAttribute(gemm_batch_k, cudaFuncAttributeMaxDynamicSharedMemorySize, SMEM);

    // ---- once-per-call prep ----
    wprep_k<<<(40 * 16384 + 255) / 256, 256>>>(Wl, Wr, Whi, Wlo);
    for (int t = 0; t < 3; t++)
        encode_k<<<(Nn[t] * 32 + 255) / 256, 256>>>(
            x_in[t], Wenc[t], benc[t], bufA + XOFF[t], Nn[t], Kin[t]);

    EL el;
    el.cumE[0] = 0;
    for (int t = 0; t < 5; t++) {
        el.src[t] = srcA[t];
        el.dst[t] = dstA[t];
        el.cumE[t + 1] = el.cumE[t] + E[t];
    }
    int Etot = el.cumE[5];
    NArr na;
    for (int ei = 0; ei < 5; ei++) {
        na.N[2 * ei] = Nn[sT[ei]];
        na.N[2 * ei + 1] = Nn[dT[ei]];
    }

    // role compaction (batched)
    cudaMemsetAsync(rankB, 0, (size_t)10 * RSTR * 4);
    mark_all_k<<<(2 * Etot + 255) / 256, 256>>>(el, Etot);
    bscan1_k<<<10 * NBLK, 1024>>>(rankB, scanB, part);
    bscan2_k<<<10, 512>>>(part);
    bscan3_k<<<10 * NBLK, 1024>>>(scanB, part, nullptr);
    bcompact_k<<<(10 * RSTR + 255) / 256, 256>>>(na);

    // CSR build (batched); bscan3 dual-writes the fill cursors
    cudaMemsetAsync(degB, 0, (size_t)5 * RSTR * 4);
    bhist_k<<<(Etot + 255) / 256, 256>>>(el, Etot);
    bscan1_k<<<5 * NBLK, 1024>>>(degB, off5, part);
    bscan2_k<<<5, 512>>>(part);
    bscan3_k<<<5 * NBLK, 1024>>>(off5, part, cur5);
    bfill_k<<<(Etot + 255) / 256, 256>>>(el, Etot);

    __half* x = bufA;
    __half* agg = bufB;

    auto makeRole = [&](int ei, int side, int l) {
        int role = 2 * ei + side;
        int po = l * 5 + ei;
        int wIdx = side ? (20 + po) : po;
        GR R;
        R.A = x + XOFF[side ? dT[ei] : sT[ei]];
        R.rowlist = listB + (size_t)role * RSTR;
        R.cntPtr = cnt + role;
        R.Bhi = Whi + (size_t)wIdx * 16384;
        R.Blo = Wlo + (size_t)wIdx * 16384;
        R.bias = side ? (br + (size_t)po * 128) : (bl + (size_t)po * 128);
        R.out = pool + POOL[role] * 128;
        return R;
    };
    auto edgeT = [&](int ei, int l) {
        int po = l * 5 + ei;
        EdgeT t;
        t.xl = pool + POOL[2 * ei] * 128;
        t.xr = pool + POOL[2 * ei + 1] * 128;
        t.csr = csrB + el.cumE[ei];
        t.off = off5 + (size_t)ei * RSTR;
        t.rank = rankB + (size_t)(2 * ei + 1) * RSTR;
        t.att = att + (size_t)po * 128;
        t.bias = cb + (size_t)po * 128;
        return t;
    };

    for (int l = 0; l < 4; l++) {
        bool last = (l == 3);
        bool skipJb = (l == 2);

        GB gb;
        int nr = 0, cum = 0;
        if (!last) {
            for (int ei = 0; ei < 5; ei++) {
                if (skipJb && ei == 1) continue;
                for (int side = 0; side < 2; side++) {
                    gb.r[nr] = makeRole(ei, side, l);
                    gb.cum[nr] = cum;
                    cum += GRIDR[2 * ei + side];
                    nr++;
                }
            }
        } else {
            for (int side = 0; side < 2; side++) {
                gb.r[nr] = makeRole(3, side, l);
                gb.cum[nr] = cum;
                cum += GRIDR[6 + side];
                nr++;
            }
        }
        gb.cum[nr] = cum;
        gb.n = nr;
        gemm_batch_k<<<cum, 256, SMEM>>>(gb);

        LayerED L;
        L.Wdec = Wdec; L.bdec = bdec; L.dec_out = (float*)d_out;
        if (!last) {
            L.tJ0 = edgeT(0, l); L.tJ1 = edgeT(2, l); L.tJ2 = edgeT(4, l);
            L.tB = edgeT(1, l);
            L.tF = edgeT(3, l);
            L.aggJ = agg + XOFF[1];
            L.aggB = agg + XOFF[0];
            L.aggF = agg + XOFF[2];
            L.doDecode = 0;
            int gJ = NJOINT / 16;                     // 30000
            int gB = skipJb ? 0 : NBASE / 16;         // 2500 or 0
            int gF = NFOOT / 16;                      // 10000
            L.bB0 = gJ;
            L.bF0 = gJ + gB;
            edge_layer_k<<<gJ + gB + gF, 256>>>(L);
            __half* tmp = x; x = agg; agg = tmp;
        } else {
            L.tJ0 = L.tJ1 = L.tJ2 = edgeT(3, l);
            L.tB = edgeT(3, l);
            L.tF = edgeT(3, l);
            L.aggJ = L.aggB = L.aggF = agg + XOFF[2];
            L.doDecode = 1;
            L.bB0 = 0;
            L.bF0 = 0;
            edge_layer_k<<<NFOOT / 16, 256>>>(L);
        }
    }
}

// round 17
// speedup vs baseline: 1.0873x; 1.0873x over previous
#include <cuda_runtime.h>
#include <cuda_fp16.h>
#include <math.h>

#define NBASE 40000
#define NJOINT 480000
#define NFOOT 160000
#define HDIM 128
#define NEG_SLOPE 0.2f
#define RSTR 481280      // padded per-role segment stride (= 470*1024)
#define NBLK 470         // 1024-elem scan blocks per segment

// ---------------- scratch (device globals; ~1.0 GB, linker-safe) ----------------
__device__ __half g_bufA[(size_t)680000 * 128];   // x / agg ping-pong (fp16, post-relu)
__device__ __half g_bufB[(size_t)680000 * 128];
__device__ __half g_pool[(size_t)1680000 * 128];  // compact xl/xr rows (fp16)
__device__ __half g_Whi[40 * 16384];              // fp16 hi/lo split of W^T ([n][k])
__device__ __half g_Wlo[40 * 16384];
__device__ int g_rank[10 * RSTR];
__device__ int g_list[10 * RSTR];
__device__ int g_scan[10 * RSTR];
__device__ int g_deg[5 * RSTR];
__device__ int g_off5[5 * RSTR];
__device__ int g_cur5[5 * RSTR];
__device__ int g_csr[960000];
__device__ int g_cnt[16];
__device__ int g_part[10 * 512];

// ---------------- weight prep: transpose + fp16 hi/lo split ----------------
__global__ void wprep_k(const float* __restrict__ Wl, const float* __restrict__ Wr,
                        __half* __restrict__ hi, __half* __restrict__ lo) {
    int idx = blockIdx.x * 256 + threadIdx.x;
    if (idx >= 40 * 16384) return;
    int m = idx >> 14, e = idx & 16383;
    int n = e >> 7, k = e & 127;
    const float* src = (m < 20) ? (Wl + (size_t)m * 16384) : (Wr + (size_t)(m - 20) * 16384);
    float v = src[k * 128 + n];
    __half h = __float2half(v);
    __half l = __float2half(v - __half2float(h));
    hi[idx] = h; lo[idx] = l;
}

// vectorized encoder (writes post-relu fp16)
__global__ void encode_k(const float* __restrict__ x, const float* __restrict__ W,
                         const float* __restrict__ b, __half* __restrict__ y, int N, int K) {
    int idx = blockIdx.x * 256 + threadIdx.x;
    if (idx >= N * 32) return;
    int n = idx >> 5, q = idx & 31;
    float4 acc = ((const float4*)b)[q];
    for (int k = 0; k < K; k++) {
        float xv = __ldg(x + (size_t)n * K + k);
        float4 w = ((const float4*)W)[k * 32 + q];
        acc.x += xv * w.x; acc.y += xv * w.y; acc.z += xv * w.z; acc.w += xv * w.w;
    }
    __half2 h0 = __floats2half2_rn(fmaxf(acc.x, 0.f), fmaxf(acc.y, 0.f));
    __half2 h1 = __floats2half2_rn(fmaxf(acc.z, 0.f), fmaxf(acc.w, 0.f));
    uint2 p;
    p.x = *(unsigned*)&h0;
    p.y = *(unsigned*)&h1;
    *(uint2*)(y + (size_t)n * 128 + q * 4) = p;
}

// ---------------- batched prep ----------------
struct EL {
    const int* src[5];
    const int* dst[5];
    int cumE[6];
};
struct NArr { int N[10]; };

__global__ void mark_all_k(EL el, int total) {
    int gi = blockIdx.x * 256 + threadIdx.x;
    if (gi >= 2 * total) return;
    int side = gi >= total;
    int j = gi - side * total;
    int t = 0;
    while (j >= el.cumE[t + 1]) t++;
    int e = j - el.cumE[t];
    int node = side ? el.dst[t][e] : el.src[t][e];
    g_rank[(2 * t + side) * RSTR + node] = 1;
}

__global__ void bscan1_k(const int* __restrict__ v, int* __restrict__ out,
                         int* __restrict__ part) {
    __shared__ int sh[1024];
    int r = blockIdx.x / NBLK, j = blockIdx.x % NBLK;
    int i = r * RSTR + j * 1024 + threadIdx.x;
    int val = v[i];
    sh[threadIdx.x] = val;
    __syncthreads();
#pragma unroll
    for (int o = 1; o < 1024; o <<= 1) {
        int t = (threadIdx.x >= o) ? sh[threadIdx.x - o] : 0;
        __syncthreads();
        sh[threadIdx.x] += t;
        __syncthreads();
    }
    int incl = sh[threadIdx.x];
    out[i] = incl - val;
    if (threadIdx.x == 1023) part[r * 512 + j] = incl;
}
__global__ void bscan2_k(int* part) {
    __shared__ int sh[512];
    int r = blockIdx.x;
    int v = (threadIdx.x < NBLK) ? part[r * 512 + threadIdx.x] : 0;
    sh[threadIdx.x] = v;
    __syncthreads();
#pragma unroll
    for (int o = 1; o < 512; o <<= 1) {
        int t = (threadIdx.x >= o) ? sh[threadIdx.x - o] : 0;
        __syncthreads();
        sh[threadIdx.x] += t;
        __syncthreads();
    }
    if (threadIdx.x < NBLK) part[r * 512 + threadIdx.x] = sh[threadIdx.x] - v;
}
__global__ void bscan3_k(int* __restrict__ out, const int* __restrict__ part,
                         int* __restrict__ cur) {
    int r = blockIdx.x / NBLK, j = blockIdx.x % NBLK;
    int i = r * RSTR + j * 1024 + threadIdx.x;
    int v = out[i] + part[r * 512 + j];
    out[i] = v;
    if (cur) cur[i] = v;
}

__global__ void bcompact_k(NArr na) {
    int i = blockIdx.x * 256 + threadIdx.x;
    if (i >= 10 * RSTR) return;
    int r = i / RSTR, li = i % RSTR;
    if (li == na.N[r]) g_cnt[r] = g_scan[i];
    if (li >= na.N[r]) return;
    if (g_rank[i]) {
        int pos = g_scan[i];
        g_list[r * RSTR + pos] = li;
        g_rank[i] = pos;
    } else {
        g_rank[i] = -1;
    }
}

__global__ void bhist_k(EL el, int total) {
    int j = blockIdx.x * 256 + threadIdx.x;
    if (j >= total) return;
    int t = 0;
    while (j >= el.cumE[t + 1]) t++;
    int e = j - el.cumE[t];
    atomicAdd(&g_deg[t * RSTR + el.dst[t][e]], 1);
}
__global__ void bfill_k(EL el, int total) {
    int j = blockIdx.x * 256 + threadIdx.x;
    if (j >= total) return;
    int t = 0;
    while (j >= el.cumE[t + 1]) t++;
    int e = j - el.cumE[t];
    int d = el.dst[t][e];
    int p = atomicAdd(&g_cur5[t * RSTR + d], 1);
    g_csr[el.cumE[t] + p] = g_rank[(2 * t) * RSTR + el.src[t][e]];
}

// ---------------- batched gather-GEMM (fp16 A exact, fp16 hi/lo W, 2-term MMA) ----------------
#define SAE 8704    // 64*136 fp16 elems (A)
#define SBE 17408   // 128*136 fp16 elems (B)
// smem: [A SAE][Bhi SBE][Blo SBE] = 43520 elems = 87040 B -> 2 CTAs/SM

#define LDSM4(R, addr) asm volatile( \
    "ldmatrix.sync.aligned.m8n8.x4.shared.b16 {%0,%1,%2,%3}, [%4];" \
    : "=r"((R)[0]), "=r"((R)[1]), "=r"((R)[2]), "=r"((R)[3]) : "r"(addr))

#define MMAF16(C, A, b0, b1) asm volatile( \
    "mma.sync.aligned.m16n8k16.row.col.f32.f16.f16.f32 " \
    "{%0,%1,%2,%3},{%4,%5,%6,%7},{%8,%9},{%0,%1,%2,%3};" \
    : "+f"((C)[0]), "+f"((C)[1]), "+f"((C)[2]), "+f"((C)[3]) \
    : "r"((A)[0]), "r"((A)[1]), "r"((A)[2]), "r"((A)[3]), "r"(b0), "r"(b1))

static __device__ __forceinline__ void cpasync16(unsigned dst, const void* src, int sz) {
    asm volatile("cp.async.cg.shared.global [%0], [%1], 16, %2;" :: "r"(dst), "l"(src), "r"(sz));
}

struct GR {
    const __half* A;
    const int* rowlist;
    const int* cntPtr;
    const __half* Bhi;
    const __half* Blo;
    const float* bias;
    __half* out;
};
struct GB { GR r[10]; int cum[11]; int n; };

__global__ void __launch_bounds__(256, 2) gemm_batch_k(GB gb) {
    int b = blockIdx.x;
    int k = 0;
    while (k < gb.n - 1 && b >= gb.cum[k + 1]) k++;
    GR R = gb.r[k];
    const int cnt = *R.cntPtr;
    const int row0 = (b - gb.cum[k]) * 64;
    if (row0 >= cnt) return;

    extern __shared__ __half smem[];
    const int tid = threadIdx.x;
    unsigned sA = (unsigned)__cvta_generic_to_shared(smem);
    unsigned sB = sA + SAE * 2;

#pragma unroll
    for (int i = 0; i < 8; i++) {
        int chunk = tid + i * 256;
        int row = chunk >> 4;
        int col = (chunk & 15) * 8;
        size_t off = (size_t)row * 128 + col;
        unsigned d = sB + (unsigned)(row * 136 + col) * 2;
        cpasync16(d, R.Bhi + off, 16);
        cpasync16(d + SBE * 2, R.Blo + off, 16);
    }
#pragma unroll
    for (int i = 0; i < 4; i++) {
        int chunk = tid + i * 256;
        int row = chunk >> 4;
        int col = (chunk & 15) * 8;
        int ok = (row0 + row) < cnt;
        int node = ok ? R.rowlist[row0 + row] : 0;
        unsigned d = sA + (unsigned)(row * 136 + col) * 2;
        cpasync16(d, R.A + (size_t)node * 128 + col, ok ? 16 : 0);
    }
    asm volatile("cp.async.commit_group;");
    asm volatile("cp.async.wait_group 0;");
    __syncthreads();

    int warp = tid >> 5, lane = tid & 31;
    int m0 = (warp >> 2) * 32;
    int n0 = (warp & 3) * 32;
    int frow = lane & 15;
    int fcolo = (lane >> 4) * 8;

    float acc[2][4][4];
#pragma unroll
    for (int a = 0; a < 2; a++)
#pragma unroll
        for (int c = 0; c < 4; c++)
#pragma unroll
            for (int r = 0; r < 4; r++) acc[a][c][r] = 0.f;

    for (int ks = 0; ks < 8; ks++) {
        int acol = ks * 16 + fcolo;
        unsigned ah[2][4];
#pragma unroll
        for (int mt = 0; mt < 2; mt++) {
            unsigned ad = sA + (unsigned)((m0 + mt * 16 + frow) * 136 + acol) * 2;
            LDSM4(ah[mt], ad);
        }
        unsigned bh[2][4], blx[2][4];
#pragma unroll
        for (int p = 0; p < 2; p++) {
            unsigned bd = sB + (unsigned)((n0 + p * 16 + frow) * 136 + acol) * 2;
            LDSM4(bh[p], bd);
            LDSM4(blx[p], bd + SBE * 2);
        }
#pragma unroll
        for (int mt = 0; mt < 2; mt++)
#pragma unroll
            for (int nt = 0; nt < 4; nt++) {
                int p = nt >> 1, o = nt & 1;
                MMAF16(acc[mt][nt], ah[mt], bh[p][o], bh[p][2 + o]);
                MMAF16(acc[mt][nt], ah[mt], blx[p][o], blx[p][2 + o]);
            }
    }

    int crow = lane >> 2, ccol = (lane & 3) * 2;
#pragma unroll
    for (int nt = 0; nt < 4; nt++) {
        int col = n0 + nt * 8 + ccol;
        float b0v = R.bias[col], b1v = R.bias[col + 1];
#pragma unroll
        for (int mt = 0; mt < 2; mt++) {
            int r = row0 + m0 + mt * 16 + crow;
            if (r < cnt)
                *(__half2*)(R.out + (size_t)r * 128 + col) =
                    __floats2half2_rn(acc[mt][nt][0] + b0v, acc[mt][nt][1] + b1v);
            if (r + 8 < cnt)
                *(__half2*)(R.out + (size_t)(r + 8) * 128 + col) =
                    __floats2half2_rn(acc[mt][nt][2] + b0v, acc[mt][nt][3] + b1v);
        }
    }
}

// ---------------- fused per-layer edge kernel (warp-per-dst, deg-1/deg-2 fast paths) ------
struct EdgeT {
    const __half* xl;
    const __half* xr;
    const int* csr;
    const int* off;
    const int* rank;
    const float* att;
    const float* bias;
};

static __device__ __forceinline__ float4 ldh4(const __half* p) {
    uint2 raw = *(const uint2*)p;
    const __half2* hp = (const __half2*)&raw;
    float2 a = __half22float2(hp[0]);
    float2 b = __half22float2(hp[1]);
    return make_float4(a.x, a.y, b.x, b.y);
}

static __device__ __forceinline__ float edge_logit(float4 xv, float4 xr4, float4 at) {
    float t0 = xv.x + xr4.x, t1 = xv.y + xr4.y, t2 = xv.z + xr4.z, t3 = xv.w + xr4.w;
    t0 = t0 > 0.f ? t0 : NEG_SLOPE * t0;
    t1 = t1 > 0.f ? t1 : NEG_SLOPE * t1;
    t2 = t2 > 0.f ? t2 : NEG_SLOPE * t2;
    t3 = t3 > 0.f ? t3 : NEG_SLOPE * t3;
    return t0 * at.x + t1 * at.y + t2 * at.z + t3 * at.w;
}

// deg>=2 online softmax; first TWO edges preloaded (x1, x2), cr preloaded
static __device__ __forceinline__ void soft_multi2(const EdgeT& t, int cr, int s0, int s1,
                                                   int lane, float4 x1, float4 x2, float4& r) {
    float4 xr4 = ldh4(t.xr + (size_t)cr * 128 + lane * 4);
    float4 at = ((const float4*)t.att)[lane];
    float p0 = edge_logit(x1, xr4, at);
    float p1 = edge_logit(x2, xr4, at);
#pragma unroll
    for (int o = 16; o; o >>= 1) {
        p0 += __shfl_xor_sync(0xffffffffu, p0, o);
        p1 += __shfl_xor_sync(0xffffffffu, p1, o);
    }
    float m = fmaxf(p0, p1);
    float w0 = __expf(p0 - m);
    float w1 = __expf(p1 - m);
    float den = w0 + w1;
    float a0 = w0 * x1.x + w1 * x2.x;
    float a1 = w0 * x1.y + w1 * x2.y;
    float a2 = w0 * x1.z + w1 * x2.z;
    float a3 = w0 * x1.w + w1 * x2.w;
    int e = s0 + 2;
    for (; e + 1 < s1; e += 2) {
        int si0 = t.csr[e], si1 = t.csr[e + 1];
        float4 y0 = ldh4(t.xl + (size_t)si0 * 128 + lane * 4);
        float4 y1 = ldh4(t.xl + (size_t)si1 * 128 + lane * 4);
        float q0 = edge_logit(y0, xr4, at);
        float q1 = edge_logit(y1, xr4, at);
#pragma unroll
        for (int o = 16; o; o >>= 1) {
            q0 += __shfl_xor_sync(0xffffffffu, q0, o);
            q1 += __shfl_xor_sync(0xffffffffu, q1, o);
        }
        float mn = fmaxf(m, fmaxf(q0, q1));
        float c = __expf(m - mn);
        float u0 = __expf(q0 - mn);
        float u1 = __expf(q1 - mn);
        den = den * c + u0 + u1;
        a0 = a0 * c + u0 * y0.x + u1 * y1.x;
        a1 = a1 * c + u0 * y0.y + u1 * y1.y;
        a2 = a2 * c + u0 * y0.z + u1 * y1.z;
        a3 = a3 * c + u0 * y0.w + u1 * y1.w;
        m = mn;
    }
    if (e < s1) {
        int si = t.csr[e];
        float4 yv = ldh4(t.xl + (size_t)si * 128 + lane * 4);
        float q = edge_logit(yv, xr4, at);
#pragma unroll
        for (int o = 16; o; o >>= 1) q += __shfl_xor_sync(0xffffffffu, q, o);
        float mn = fmaxf(m, q);
        float c = __expf(m - mn);
        float w = __expf(q - mn);
        den = den * c + w;
        a0 = a0 * c + w * yv.x;
        a1 = a1 * c + w * yv.y;
        a2 = a2 * c + w * yv.z;
        a3 = a3 * c + w * yv.w;
    }
    float inv = 1.f / den;
    r.x += a0 * inv; r.y += a1 * inv; r.z += a2 * inv; r.w += a3 * inv;
}

// single edge-type: deg-1 fast path + deg-2 prefetch
static __device__ __forceinline__ void proc_fast(const EdgeT& t, int d, int lane, float4& r) {
    float4 bb = ((const float4*)t.bias)[lane];
    r.x += bb.x; r.y += bb.y; r.z += bb.z; r.w += bb.w;
    int s0 = t.off[d], s1 = t.off[d + 1];
    if (s1 <= s0) return;
    int deg = s1 - s0;
    int cr = t.rank[d];                 // independent load, issues in parallel with csr chain
    int fi = t.csr[s0];
    int fi2 = (deg > 1) ? t.csr[s0 + 1] : fi;
    float4 x1 = ldh4(t.xl + (size_t)fi * 128 + lane * 4);
    if (deg == 1) {
        r.x += x1.x; r.y += x1.y; r.z += x1.z; r.w += x1.w;   // softmax of 1 elem == 1
        return;
    }
    float4 x2 = ldh4(t.xl + (size_t)fi2 * 128 + lane * 4);
    soft_multi2(t, cr, s0, s1, lane, x1, x2, r);
}

// joint dst: three edge types with cross-type prefetch of off/rank/csr/first-two-xl
static __device__ __forceinline__ void edge_joint3(const EdgeT& tA, const EdgeT& tB,
                                                   const EdgeT& tC, int d, int lane,
                                                   float4& r) {
    int s0a = tA.off[d], s1a = tA.off[d + 1];
    int s0b = tB.off[d], s1b = tB.off[d + 1];
    int s0c = tC.off[d], s1c = tC.off[d + 1];
    {
        float4 b0 = ((const float4*)tA.bias)[lane];
        float4 b1 = ((const float4*)tB.bias)[lane];
        float4 b2 = ((const float4*)tC.bias)[lane];
        r.x += b0.x + b1.x + b2.x;
        r.y += b0.y + b1.y + b2.y;
        r.z += b0.z + b1.z + b2.z;
        r.w += b0.w + b1.w + b2.w;
    }
    int dA = s1a - s0a, dB = s1b - s0b, dC = s1c - s0c;
    int crA = 0, crB = 0, crC = 0;
    if (dA > 1) crA = tA.rank[d];
    if (dB > 1) crB = tB.rank[d];
    if (dC > 1) crC = tC.rank[d];
    int fiA = 0, fiB = 0, fiC = 0, fiA2 = 0, fiB2 = 0, fiC2 = 0;
    if (dA > 0) fiA = tA.csr[s0a];
    if (dB > 0) fiB = tB.csr[s0b];
    if (dC > 0) fiC = tC.csr[s0c];
    if (dA > 1) fiA2 = tA.csr[s0a + 1];
    if (dB > 1) fiB2 = tB.csr[s0b + 1];
    if (dC > 1) fiC2 = tC.csr[s0c + 1];
    float4 xA = make_float4(0.f, 0.f, 0.f, 0.f);
    float4 xB = make_float4(0.f, 0.f, 0.f, 0.f);
    float4 xC = make_float4(0.f, 0.f, 0.f, 0.f);
    float4 xA2 = xA, xB2 = xB, xC2 = xC;
    if (dA > 0) xA = ldh4(tA.xl + (size_t)fiA * 128 + lane * 4);
    if (dB > 0) xB = ldh4(tB.xl + (size_t)fiB * 128 + lane * 4);
    if (dC > 0) xC = ldh4(tC.xl + (size_t)fiC * 128 + lane * 4);
    if (dA > 1) xA2 = ldh4(tA.xl + (size_t)fiA2 * 128 + lane * 4);
    if (dB > 1) xB2 = ldh4(tB.xl + (size_t)fiB2 * 128 + lane * 4);
    if (dC > 1) xC2 = ldh4(tC.xl + (size_t)fiC2 * 128 + lane * 4);
    if (dA == 1) { r.x += xA.x; r.y += xA.y; r.z += xA.z; r.w += xA.w; }
    else if (dA > 1) soft_multi2(tA, crA, s0a, s1a, lane, xA, xA2, r);
    if (dB == 1) { r.x += xB.x; r.y += xB.y; r.z += xB.z; r.w += xB.w; }
    else if (dB > 1) soft_multi2(tB, crB, s0b, s1b, lane, xB, xB2, r);
    if (dC == 1) { r.x += xC.x; r.y += xC.y; r.z += xC.z; r.w += xC.w; }
    else if (dC > 1) soft_multi2(tC, crC, s0c, s1c, lane, xC, xC2, r);
}

// store with fused relu (activations consumed post-relu everywhere)
static __device__ __forceinline__ void store_agg(__half* agg, int d, int lane, float4 r) {
    __half2 p0 = __floats2half2_rn(fmaxf(r.x, 0.f), fmaxf(r.y, 0.f));
    __half2 p1 = __floats2half2_rn(fmaxf(r.z, 0.f), fmaxf(r.w, 0.f));
    uint2 packed;
    packed.x = *(unsigned*)&p0;
    packed.y = *(unsigned*)&p1;
    *(uint2*)(agg + (size_t)d * 128 + lane * 4) = packed;
}

struct LayerED {
    EdgeT tJ0, tJ1, tJ2;
    EdgeT tB;
    EdgeT tF;
    __half *aggJ, *aggB, *aggF;
    int bB0, bF0;
    const float* Wdec;
    const float* bdec;
    float* dec_out;
    int doDecode;
};

__global__ void edge_layer_k(LayerED L) {
    int blk = blockIdx.x;
    int w = threadIdx.x >> 5;
    int lane = threadIdx.x & 31;
    float4 r = make_float4(0.f, 0.f, 0.f, 0.f);
    if (blk < L.bB0) {
        int d = blk * 8 + w;
        edge_joint3(L.tJ0, L.tJ1, L.tJ2, d, lane, r);
        store_agg(L.aggJ, d, lane, r);
    } else if (blk < L.bF0) {
        int d = (blk - L.bB0) * 8 + w;
        proc_fast(L.tB, d, lane, r);
        store_agg(L.aggB, d, lane, r);
    } else {
        int d = (blk - L.bF0) * 8 + w;
        proc_fast(L.tF, d, lane, r);
        if (!L.doDecode) {
            store_agg(L.aggF, d, lane, r);
        } else {
            r.x = fmaxf(r.x, 0.f); r.y = fmaxf(r.y, 0.f);
            r.z = fmaxf(r.z, 0.f); r.w = fmaxf(r.w, 0.f);
            int h = lane * 4;
            const float* W = L.Wdec;
            float s0 = r.x * W[(h + 0) * 3 + 0] + r.y * W[(h + 1) * 3 + 0] + r.z * W[(h + 2) * 3 + 0] + r.w * W[(h + 3) * 3 + 0];
            float s1 = r.x * W[(h + 0) * 3 + 1] + r.y * W[(h + 1) * 3 + 1] + r.z * W[(h + 2) * 3 + 1] + r.w * W[(h + 3) * 3 + 1];
            float s2 = r.x * W[(h + 0) * 3 + 2] + r.y * W[(h + 1) * 3 + 2] + r.z * W[(h + 2) * 3 + 2] + r.w * W[(h + 3) * 3 + 2];
#pragma unroll
            for (int o = 16; o; o >>= 1) {
                s0 += __shfl_xor_sync(0xffffffffu, s0, o);
                s1 += __shfl_xor_sync(0xffffffffu, s1, o);
                s2 += __shfl_xor_sync(0xffffffffu, s2, o);
            }
            if (lane == 0) {
                L.dec_out[d * 3 + 0] = s0 + L.bdec[0];
                L.dec_out[d * 3 + 1] = s1 + L.bdec[1];
                L.dec_out[d * 3 + 2] = s2 + L.bdec[2];
            }
        }
    }
}

// ---------------- host orchestration ----------------
extern "C" void kernel_launch(void* const* d_in, const int* in_sizes, int n_in,
                              void* d_out, int out_size) {
    int I[27];
    if (in_sizes[1] == 768) {
        const int m[27] = {0, 3, 6, 1, 2, 4, 5, 7, 8,
                           19, 20, 21, 22, 23, 24, 25, 26,
                           9, 10, 11, 12, 13, 14, 15, 16, 17, 18};
        for (int i = 0; i < 27; i++) I[i] = m[i];
    } else {
        for (int i = 0; i < 27; i++) I[i] = i;
    }

    const float* x_in[3] = {(const float*)d_in[I[0]], (const float*)d_in[I[1]], (const float*)d_in[I[2]]};
    const float* Wenc[3] = {(const float*)d_in[I[3]], (const float*)d_in[I[5]], (const float*)d_in[I[7]]};
    const float* benc[3] = {(const float*)d_in[I[4]], (const float*)d_in[I[6]], (const float*)d_in[I[8]]};
    const float* Wl = (const float*)d_in[I[9]];
    const float* bl = (const float*)d_in[I[10]];
    const float* Wr = (const float*)d_in[I[11]];
    const float* br = (const float*)d_in[I[12]];
    const float* att = (const float*)d_in[I[13]];
    const float* cb = (const float*)d_in[I[14]];
    const float* Wdec = (const float*)d_in[I[15]];
    const float* bdec = (const float*)d_in[I[16]];
    const int *srcA[5], *dstA[5];
    int E[5];
    for (int t = 0; t < 5; t++) {
        srcA[t] = (const int*)d_in[I[17 + 2 * t]];
        dstA[t] = (const int*)d_in[I[18 + 2 * t]];
        E[t] = in_sizes[I[17 + 2 * t]];
    }

    __half *bufA, *bufB, *pool, *Whi, *Wlo;
    int *rankB, *listB, *scanB, *degB, *off5, *cur5, *csrB, *cnt, *part;
    cudaGetSymbolAddress((void**)&bufA, g_bufA);
    cudaGetSymbolAddress((void**)&bufB, g_bufB);
    cudaGetSymbolAddress((void**)&pool, g_pool);
    cudaGetSymbolAddress((void**)&Whi, g_Whi);
    cudaGetSymbolAddress((void**)&Wlo, g_Wlo);
    cudaGetSymbolAddress((void**)&rankB, g_rank);
    cudaGetSymbolAddress((void**)&listB, g_list);
    cudaGetSymbolAddress((void**)&scanB, g_scan);
    cudaGetSymbolAddress((void**)&degB, g_deg);
    cudaGetSymbolAddress((void**)&off5, g_off5);
    cudaGetSymbolAddress((void**)&cur5, g_cur5);
    cudaGetSymbolAddress((void**)&csrB, g_csr);
    cudaGetSymbolAddress((void**)&cnt, g_cnt);
    cudaGetSymbolAddress((void**)&part, g_part);

    const int Nn[3] = {NBASE, NJOINT, NFOOT};
    const int Kin[3] = {6, 2, 4};
    const size_t XOFF[3] = {0, (size_t)NBASE * 128, (size_t)(NBASE + NJOINT) * 128};
    const int sT[5] = {0, 1, 1, 1, 2};
    const int dT[5] = {1, 0, 1, 2, 1};
    const size_t POOL[10] = {0, 40000, 200000, 360000, 400000, 720000, 1040000, 1200000, 1360000, 1520000};
    const int GRIDR[10] = {625, 2500, 2500, 625, 5000, 5000, 2500, 2500, 2500, 2500};

    const int SMEM = (SAE + 2 * SBE) * 2;   // 87040 B -> 2 CTAs/SM
    cudaFuncSetAttribute(gemm_batch_k, cudaFuncAttributeMaxDynamicSharedMemorySize, SMEM);

    // ---- once-per-call prep ----
    wprep_k<<<(40 * 16384 + 255) / 256, 256>>>(Wl, Wr, Whi, Wlo);
    for (int t = 0; t < 3; t++)
        encode_k<<<(Nn[t] * 32 + 255) / 256, 256>>>(
            x_in[t], Wenc[t], benc[t], bufA + XOFF[t], Nn[t], Kin[t]);

    EL el;
    el.cumE[0] = 0;
    for (int t = 0; t < 5; t++) {
        el.src[t] = srcA[t];
        el.dst[t] = dstA[t];
        el.cumE[t + 1] = el.cumE[t] + E[t];
    }
    int Etot = el.cumE[5];
    NArr na;
    for (int ei = 0; ei < 5; ei++) {
        na.N[2 * ei] = Nn[sT[ei]];
        na.N[2 * ei + 1] = Nn[dT[ei]];
    }

    // role compaction (batched)
    cudaMemsetAsync(rankB, 0, (size_t)10 * RSTR * 4);
    mark_all_k<<<(2 * Etot + 255) / 256, 256>>>(el, Etot);
    bscan1_k<<<10 * NBLK, 1024>>>(rankB, scanB, part);
    bscan2_k<<<10, 512>>>(part);
    bscan3_k<<<10 * NBLK, 1024>>>(scanB, part, nullptr);
    bcompact_k<<<(10 * RSTR + 255) / 256, 256>>>(na);

    // CSR build (batched); bscan3 dual-writes the fill cursors
    cudaMemsetAsync(degB, 0, (size_t)5 * RSTR * 4);
    bhist_k<<<(Etot + 255) / 256, 256>>>(el, Etot);
    bscan1_k<<<5 * NBLK, 1024>>>(degB, off5, part);
    bscan2_k<<<5, 512>>>(part);
    bscan3_k<<<5 * NBLK, 1024>>>(off5, part, cur5);
    bfill_k<<<(Etot + 255) / 256, 256>>>(el, Etot);

    __half* x = bufA;
    __half* agg = bufB;

    auto makeRole = [&](int ei, int side, int l) {
        int role = 2 * ei + side;
        int po = l * 5 + ei;
        int wIdx = side ? (20 + po) : po;
        GR R;
        R.A = x + XOFF[side ? dT[ei] : sT[ei]];
        R.rowlist = listB + (size_t)role * RSTR;
        R.cntPtr = cnt + role;
        R.Bhi = Whi + (size_t)wIdx * 16384;
        R.Blo = Wlo + (size_t)wIdx * 16384;
        R.bias = side ? (br + (size_t)po * 128) : (bl + (size_t)po * 128);
        R.out = pool + POOL[role] * 128;
        return R;
    };
    auto edgeT = [&](int ei, int l) {
        int po = l * 5 + ei;
        EdgeT t;
        t.xl = pool + POOL[2 * ei] * 128;
        t.xr = pool + POOL[2 * ei + 1] * 128;
        t.csr = csrB + el.cumE[ei];
        t.off = off5 + (size_t)ei * RSTR;
        t.rank = rankB + (size_t)(2 * ei + 1) * RSTR;
        t.att = att + (size_t)po * 128;
        t.bias = cb + (size_t)po * 128;
        return t;
    };

    for (int l = 0; l < 4; l++) {
        bool last = (l == 3);
        bool skipJb = (l == 2);

        GB gb;
        int nr = 0, cum = 0;
        if (!last) {
            for (int ei = 0; ei < 5; ei++) {
                if (skipJb && ei == 1) continue;
                for (int side = 0; side < 2; side++) {
                    gb.r[nr] = makeRole(ei, side, l);
                    gb.cum[nr] = cum;
                    cum += GRIDR[2 * ei + side];
                    nr++;
                }
            }
        } else {
            for (int side = 0; side < 2; side++) {
                gb.r[nr] = makeRole(3, side, l);
                gb.cum[nr] = cum;
                cum += GRIDR[6 + side];
                nr++;
            }
        }
        gb.cum[nr] = cum;
        gb.n = nr;
        gemm_batch_k<<<cum, 256, SMEM>>>(gb);

        LayerED L;
        L.Wdec = Wdec; L.bdec = bdec; L.dec_out = (float*)d_out;
        if (!last) {
            L.tJ0 = edgeT(0, l); L.tJ1 = edgeT(2, l); L.tJ2 = edgeT(4, l);
            L.tB = edgeT(1, l);
            L.tF = edgeT(3, l);
            L.aggJ = agg + XOFF[1];
            L.aggB = agg + XOFF[0];
            L.aggF = agg + XOFF[2];
            L.doDecode = 0;
            int gJ = NJOINT / 8;
            int gB = skipJb ? 0 : NBASE / 8;
            int gF = NFOOT / 8;
            L.bB0 = gJ;
            L.bF0 = gJ + gB;
            edge_layer_k<<<gJ + gB + gF, 256>>>(L);
            __half* tmp = x; x = agg; agg = tmp;
        } else {
            L.tJ0 = L.tJ1 = L.tJ2 = edgeT(3, l);
            L.tB = edgeT(3, l);
            L.tF = edgeT(3, l);
            L.aggJ = L.aggB = L.aggF = agg + XOFF[2];
            L.doDecode = 1;
            L.bB0 = 0;
            L.bF0 = 0;
            edge_layer_k<<<NFOOT / 8, 256>>>(L);
        }
    }
}